// round 9
// baseline (speedup 1.0000x reference)
#include <cuda_runtime.h>

#define N_NODES 20000
#define N_EDGES 320000
#define E_TOT   (N_EDGES + N_NODES)
#define N_GRAPHS 64
#define GEMM_TILE 16
#define GPAD 20
#define SPS 68

// PDL: trigger lets dependents launch early; wait fences predecessor's data.
#define PDL_TRIGGER() asm volatile("griddepcontrol.launch_dependents;" ::: "memory")
#define PDL_WAIT()    asm volatile("griddepcontrol.wait;" ::: "memory")

// ---------------- scratch (device globals; no allocation allowed) ----------
// INVARIANT: g_deg is zero at kernel_launch entry (zero at module load;
// re-zeroed by the tail of k_final). g_pool zeroed by k_hist_setup.
__device__ float  g_als1[N_NODES * 8];
__device__ float  g_ald1[N_NODES * 8];
__device__ float4 g_x4[N_NODES];
__device__ float4 g_o14[N_NODES * 16];
__device__ float4 g_t24[N_NODES * 16];
__device__ float  g_als2[N_NODES];
__device__ float  g_ald2[N_NODES];
__device__ float4 g_va4[16];
__device__ float4 g_vd4[16];
__device__ int    g_deg[N_NODES];
__device__ int    g_fill[N_NODES];       // seeded to rowstart by the scan
__device__ int    g_rowstart[N_NODES + 1];
__device__ int    g_csr[E_TOT];
__device__ float  g_pool[N_GRAPHS * 512];
__device__ int    g_cnt[N_GRAPHS];

// ============ K1: hist(4-edge unroll) + va + counts + pool-zero =============
__global__ void k_hist_setup(const int* __restrict__ ei,
                             const float* __restrict__ W2,
                             const float* __restrict__ as2, const float* __restrict__ ad2,
                             const int* __restrict__ batch) {
    PDL_TRIGGER();
    int b = blockIdx.x, t = threadIdx.x;
    if (b < 333) {
        int base = b * 1024 + t;
        int dst[4];
#pragma unroll
        for (int j = 0; j < 4; j++) {
            int e = base + j * 256;
            if (e < E_TOT) dst[j] = (e < N_EDGES) ? ei[N_EDGES + e] : (e - N_EDGES);
            else dst[j] = -1;
        }
#pragma unroll
        for (int j = 0; j < 4; j++)
            if (dst[j] >= 0) atomicAdd(&g_deg[dst[j]], 1);
    } else if (b == 333) {
        if (t >= 32 && t < 96) {
            int g = t - 32;
            int lo = 0, hi = N_NODES;
            while (lo < hi) { int m = (lo + hi) >> 1; if (batch[m] < g) lo = m + 1; else hi = m; }
            int s = lo;
            lo = 0; hi = N_NODES;
            int g1 = g + 1;
            while (lo < hi) { int m = (lo + hi) >> 1; if (batch[m] < g1) lo = m + 1; else hi = m; }
            g_cnt[g] = lo - s;
        }
    } else if (b < 342) {
        int warp = (b - 334) * 8 + (t >> 5);     // 0..63
        int lane = t & 31;
        float s = 0.f, d = 0.f;
        for (int c = lane; c < 512; c += 32) {
            float w = W2[warp * 512 + c];
            s += w * as2[c];
            d += w * ad2[c];
        }
        for (int off = 16; off; off >>= 1) {
            s += __shfl_down_sync(0xffffffffu, s, off);
            d += __shfl_down_sync(0xffffffffu, d, off);
        }
        if (lane == 0) { ((float*)g_va4)[warp] = s; ((float*)g_vd4)[warp] = d; }
    } else {
        int idx = (b - 342) * 256 + t;           // 128*256 == 32768 exactly
        g_pool[idx] = 0.f;
    }
}

// ============ K2: block 0 = scan (waits); blocks 1..157 = al1 (no deps!) =====
__global__ void __launch_bounds__(1024)
k_scan_al1(const float* __restrict__ x, const float* __restrict__ W1,
           const float* __restrict__ as1, const float* __restrict__ ad1) {
    PDL_TRIGGER();
    int b = blockIdx.x, t = threadIdx.x;
    if (b == 0) {
        PDL_WAIT();                               // needs g_deg from K1
        __shared__ int sw[32];
        int lane = t & 31, w = t >> 5;
        int v[20];
#pragma unroll
        for (int k = 0; k < 20; k++) {
            int i = k * 1024 + t;
            v[k] = (i < N_NODES) ? g_deg[i] : 0;
        }
        int running = 0;
#pragma unroll
        for (int k = 0; k < 20; k++) {
            int s = v[k];
#pragma unroll
            for (int off = 1; off < 32; off <<= 1) {
                int n = __shfl_up_sync(0xffffffffu, s, off);
                if (lane >= off) s += n;
            }
            if (lane == 31) sw[w] = s;
            __syncthreads();
            if (w == 0) {
                int p = sw[lane];
#pragma unroll
                for (int off = 1; off < 32; off <<= 1) {
                    int n = __shfl_up_sync(0xffffffffu, p, off);
                    if (lane >= off) p += n;
                }
                sw[lane] = p;
            }
            __syncthreads();
            int ex = running + (w ? sw[w - 1] : 0) + s - v[k];
            int i = k * 1024 + t;
            if (i < N_NODES) { g_rowstart[i] = ex; g_fill[i] = ex; }
            running += sw[31];
            __syncthreads();
        }
        if (t == 0) g_rowstart[N_NODES] = running;
    } else {
        // al1 depends only on harness inputs: compute P locally, no wait.
        __shared__ float sPs[24], sPd[24];
        if (t < 24) {
            int h = t / 3, d = t % 3;
            float ps = 0.f, pd = 0.f;
            for (int c = 0; c < 8; c++) {
                float w = W1[d * 64 + h * 8 + c];
                ps += w * as1[h * 8 + c];
                pd += w * ad1[h * 8 + c];
            }
            sPs[t] = ps;
            sPd[t] = pd;
        }
        __syncthreads();
        int idx = (b - 1) * 1024 + t;
        if (idx < N_NODES * 8) {
            int n = idx >> 3, h = idx & 7;
            float x0 = x[n * 3], x1 = x[n * 3 + 1], x2 = x[n * 3 + 2];
            g_als1[idx] = x0 * sPs[h * 3] + x1 * sPs[h * 3 + 1] + x2 * sPs[h * 3 + 2];
            g_ald1[idx] = x0 * sPd[h * 3] + x1 * sPd[h * 3 + 1] + x2 * sPd[h * 3 + 2];
            if (h == 0) g_x4[n] = make_float4(x0, x1, x2, 0.f);
        }
    }
}

// ============ K3: scatter; edge loads (inputs) hoisted before the wait =======
__global__ void k_scatter(const int* __restrict__ ei) {
    PDL_TRIGGER();
    int base = blockIdx.x * 1024 + threadIdx.x;
    int src[4], dst[4];
#pragma unroll
    for (int j = 0; j < 4; j++) {
        int e = base + j * 256;
        if (e < E_TOT) {
            if (e < N_EDGES) { src[j] = ei[e]; dst[j] = ei[N_EDGES + e]; }
            else             { src[j] = e - N_EDGES; dst[j] = src[j]; }
        } else dst[j] = -1;
    }
    PDL_WAIT();                                   // needs g_fill from scan
#pragma unroll
    for (int j = 0; j < 4; j++) {
        if (dst[j] >= 0) {
            int pos = atomicAdd(&g_fill[dst[j]], 1);
            g_csr[pos] = src[j];
        }
    }
}

// ============ layer-1 aggregate (R6 v3: 16 lanes/node, measured best) ========
__global__ void k_agg1(const float* __restrict__ W1, const float* __restrict__ b1) {
    PDL_TRIGGER();
    PDL_WAIT();                                   // needs csr/als1/ald1/x4
    int gidx = blockIdx.x * 256 + threadIdx.x;    // exactly N_NODES*16 threads
    int n = gidx >> 4;
    int l = gidx & 15;          // lane-in-node
    int h = l >> 1, p = l & 1;  // head, half
    int s0 = g_rowstart[n], s1 = g_rowstart[n + 1];
    int half0 = (s1 - s0 + 1) >> 1;
    int a = p ? (s0 + half0) : s0;
    int bnd = p ? s1 : (s0 + half0);
    float ald = g_ald1[n * 8 + h];
    float wsum = 0.f, xa0 = 0.f, xa1 = 0.f, xa2 = 0.f;
    int i = a;
    for (; i + 2 <= bnd; i += 2) {
        int src0 = g_csr[i], src1 = g_csr[i + 1];
        float e0 = g_als1[src0 * 8 + h] + ald;
        float e1 = g_als1[src1 * 8 + h] + ald;
        float4 xv0 = g_x4[src0];
        float4 xv1 = g_x4[src1];
        e0 = (e0 > 0.f) ? e0 : 0.2f * e0;
        e1 = (e1 > 0.f) ? e1 : 0.2f * e1;
        float w0 = __expf(e0), w1 = __expf(e1);
        wsum += w0 + w1;
        xa0 += w0 * xv0.x + w1 * xv1.x;
        xa1 += w0 * xv0.y + w1 * xv1.y;
        xa2 += w0 * xv0.z + w1 * xv1.z;
    }
    if (i < bnd) {
        int src = g_csr[i];
        float e = g_als1[src * 8 + h] + ald;
        float4 xv = g_x4[src];
        e = (e > 0.f) ? e : 0.2f * e;
        float w = __expf(e);
        wsum += w;
        xa0 += w * xv.x; xa1 += w * xv.y; xa2 += w * xv.z;
    }
    wsum += __shfl_xor_sync(0xffffffffu, wsum, 1);
    xa0  += __shfl_xor_sync(0xffffffffu, xa0, 1);
    xa1  += __shfl_xor_sync(0xffffffffu, xa1, 1);
    xa2  += __shfl_xor_sync(0xffffffffu, xa2, 1);
    float inv = 1.f / wsum;
    xa0 *= inv; xa1 *= inv; xa2 *= inv;
    const float4 w0v = *(const float4*)&W1[4 * l];
    const float4 w1v = *(const float4*)&W1[64 + 4 * l];
    const float4 w2v = *(const float4*)&W1[128 + 4 * l];
    const float4 bv  = *(const float4*)&b1[4 * l];
    float4 o;
    o.x = xa0 * w0v.x + xa1 * w1v.x + xa2 * w2v.x + bv.x;
    o.y = xa0 * w0v.y + xa1 * w1v.y + xa2 * w2v.y + bv.y;
    o.z = xa0 * w0v.z + xa1 * w1v.z + xa2 * w2v.z + bv.z;
    o.w = xa0 * w0v.w + xa1 * w1v.w + xa2 * w2v.w + bv.w;
    o.x = (o.x > 0.f) ? o.x : (__expf(o.x) - 1.f);
    o.y = (o.y > 0.f) ? o.y : (__expf(o.y) - 1.f);
    o.z = (o.z > 0.f) ? o.z : (__expf(o.z) - 1.f);
    o.w = (o.w > 0.f) ? o.w : (__expf(o.w) - 1.f);
    g_o14[n * 16 + l] = o;
    float4 va = g_va4[l], vd = g_vd4[l];
    float ps2 = o.x * va.x + o.y * va.y + o.z * va.z + o.w * va.w;
    float pd2 = o.x * vd.x + o.y * vd.y + o.z * vd.z + o.w * vd.w;
#pragma unroll
    for (int off = 8; off; off >>= 1) {
        ps2 += __shfl_down_sync(0xffffffffu, ps2, off);
        pd2 += __shfl_down_sync(0xffffffffu, pd2, off);
    }
    if (l == 0) { g_als2[n] = ps2; g_ald2[n] = pd2; }
}

// ============ layer-2 aggregate: 4-edge x float4-column gather ===============
__global__ void k_agg2() {
    PDL_TRIGGER();
    PDL_WAIT();                                   // needs o14/als2/ald2
    __shared__ float sw[64];
    __shared__ int   ssrc[64];
    __shared__ float4 sacc[32];
    __shared__ float swsum[2];
    int n = blockIdx.x;
    int t = threadIdx.x;  // 64
    int q = t & 15, r = t >> 4;
    int s0 = g_rowstart[n], s1 = g_rowstart[n + 1];
    float ald = g_ald2[n];
    float wsum = 0.f;
    float4 acc = make_float4(0.f, 0.f, 0.f, 0.f);
    for (int base = s0; base < s1; base += 64) {
        int i = base + t;
        float w = 0.f;
        int src = 0;
        if (i < s1) {
            src = g_csr[i];
            float e = g_als2[src] + ald;
            e = (e > 0.f) ? e : 0.2f * e;
            w = __expf(e);
        }
        __syncthreads();
        sw[t] = w;
        ssrc[t] = src;
        wsum += w;
        __syncthreads();
        int m = (s1 - base < 64) ? (s1 - base) : 64;
        for (int j = 0; j < m; j += 4) {
            int jr = j + r;
            if (jr < m) {
                float wj = sw[jr];
                float4 v = g_o14[ssrc[jr] * 16 + q];
                acc.x += wj * v.x; acc.y += wj * v.y;
                acc.z += wj * v.z; acc.w += wj * v.w;
            }
        }
    }
    float ws = wsum;
#pragma unroll
    for (int off = 16; off; off >>= 1) ws += __shfl_down_sync(0xffffffffu, ws, off);
    if ((t & 31) == 0) swsum[t >> 5] = ws;
    if (t >= 32) sacc[t - 32] = acc;
    __syncthreads();
    if (t < 32) {
        float4 o = sacc[t];
        acc.x += o.x; acc.y += o.y; acc.z += o.z; acc.w += o.w;
        acc.x += __shfl_down_sync(0xffffffffu, acc.x, 16);
        acc.y += __shfl_down_sync(0xffffffffu, acc.y, 16);
        acc.z += __shfl_down_sync(0xffffffffu, acc.z, 16);
        acc.w += __shfl_down_sync(0xffffffffu, acc.w, 16);
        if (t < 16) {
            float inv = 1.f / (swsum[0] + swsum[1]);
            acc.x *= inv; acc.y *= inv; acc.z *= inv; acc.w *= inv;
            g_t24[n * 16 + t] = acc;
        }
    }
}

// ============ gemm2: W2 register load hoisted before wait (overlaps agg2) ====
__global__ void __launch_bounds__(512, 1)
k_gemm2(const float* __restrict__ W2, const float* __restrict__ b2,
        const int* __restrict__ batch) {
    PDL_TRIGGER();
    __shared__ __align__(16) float shT[2][64 * GPAD];
    __shared__ int sbat[2][GEMM_TILE];
    const float* t2 = (const float*)g_t24;
    int c = threadIdx.x;
    float w[64];
#pragma unroll
    for (int k = 0; k < 64; k++) w[k] = W2[k * 512 + c];   // inputs: pre-wait
    float b2c = b2[c];
    const int NT = N_NODES / GEMM_TILE;  // 1250
    int kk = c & 63, np = (c >> 6) * 2;
    int tile = blockIdx.x;
    if (c < GEMM_TILE) sbat[0][c] = batch[tile * GEMM_TILE + c];
    PDL_WAIT();                                   // needs g_t24 from agg2
    float r0 = t2[(tile * GEMM_TILE + np) * 64 + kk];
    float r1 = t2[(tile * GEMM_TILE + np + 1) * 64 + kk];
    shT[0][kk * GPAD + np]     = r0;
    shT[0][kk * GPAD + np + 1] = r1;
    __syncthreads();
    int buf = 0;
    while (true) {
        int next = tile + (int)gridDim.x;
        bool has_next = (next < NT);
        int nb = 0;
        if (has_next) {
            r0 = t2[(next * GEMM_TILE + np) * 64 + kk];
            r1 = t2[(next * GEMM_TILE + np + 1) * 64 + kk];
            if (c < GEMM_TILE) nb = batch[next * GEMM_TILE + c];
        }
        unsigned long long acc[8];
#pragma unroll
        for (int i = 0; i < 8; i++) acc[i] = 0ull;
#pragma unroll
        for (int k = 0; k < 64; k++) {
            unsigned long long wp;
            asm("mov.b64 %0, {%1, %1};" : "=l"(wp) : "f"(w[k]));
            const ulonglong2* row = reinterpret_cast<const ulonglong2*>(&shT[buf][k * GPAD]);
            ulonglong2 q0 = row[0];
            ulonglong2 q1 = row[1];
            ulonglong2 q2 = row[2];
            ulonglong2 q3 = row[3];
            asm("fma.rn.f32x2 %0, %1, %2, %0;" : "+l"(acc[0]) : "l"(q0.x), "l"(wp));
            asm("fma.rn.f32x2 %0, %1, %2, %0;" : "+l"(acc[1]) : "l"(q0.y), "l"(wp));
            asm("fma.rn.f32x2 %0, %1, %2, %0;" : "+l"(acc[2]) : "l"(q1.x), "l"(wp));
            asm("fma.rn.f32x2 %0, %1, %2, %0;" : "+l"(acc[3]) : "l"(q1.y), "l"(wp));
            asm("fma.rn.f32x2 %0, %1, %2, %0;" : "+l"(acc[4]) : "l"(q2.x), "l"(wp));
            asm("fma.rn.f32x2 %0, %1, %2, %0;" : "+l"(acc[5]) : "l"(q2.y), "l"(wp));
            asm("fma.rn.f32x2 %0, %1, %2, %0;" : "+l"(acc[6]) : "l"(q3.x), "l"(wp));
            asm("fma.rn.f32x2 %0, %1, %2, %0;" : "+l"(acc[7]) : "l"(q3.y), "l"(wp));
        }
        float vals[16];
#pragma unroll
        for (int i = 0; i < 8; i++)
            asm("mov.b64 {%0, %1}, %2;" : "=f"(vals[2 * i]), "=f"(vals[2 * i + 1]) : "l"(acc[i]));
        int bprev = sbat[buf][0];
        float run = 0.f;
#pragma unroll
        for (int i = 0; i < GEMM_TILE; i++) {
            float o = vals[i] + b2c;
            o = (o > 0.f) ? o : (__expf(o) - 1.f);  // elu
            int bg = sbat[buf][i];
            if (bg != bprev) {
                atomicAdd(&g_pool[bprev * 512 + c], run);
                run = 0.f;
                bprev = bg;
            }
            run += o;
        }
        atomicAdd(&g_pool[bprev * 512 + c], run);
        if (!has_next) break;
        int nbuf = buf ^ 1;
        shT[nbuf][kk * GPAD + np]     = r0;
        shT[nbuf][kk * GPAD + np + 1] = r1;
        if (c < GEMM_TILE) sbat[nbuf][c] = nb;
        __syncthreads();
        buf = nbuf;
        tile = next;
    }
}

// ============ final v2 (+ deg-zero behind the wait) ==========================
__global__ void k_final(const float* __restrict__ Wo, const float* __restrict__ bo,
                        float* __restrict__ out) {
    PDL_WAIT();                                   // needs g_pool; also fences
    int b = blockIdx.x;                           // g_deg-zero after scan read
    if (b < 64) {
        __shared__ float sP[64 * SPS];
        __shared__ float sW[64 * 8];
        __shared__ float sInv[64];
        int tid = threadIdx.x;           // 512
        int g = tid >> 3, j = tid & 7;
        int c = b * 8 + j;
        if (tid < 64) sInv[tid] = 1.f / fmaxf((float)g_cnt[tid], 1.f);
        __syncthreads();
        int kk0 = (tid & 7) * 8;
        float invg = sInv[g];
        float acc = 0.f;
#pragma unroll 1
        for (int kt = 0; kt < 8; kt++) {
            float4 p0 = *(const float4*)&g_pool[g * 512 + kt * 64 + kk0];
            float4 p1 = *(const float4*)&g_pool[g * 512 + kt * 64 + kk0 + 4];
            p0.x *= invg; p0.y *= invg; p0.z *= invg; p0.w *= invg;
            p1.x *= invg; p1.y *= invg; p1.z *= invg; p1.w *= invg;
            *(float4*)&sP[g * SPS + kk0]     = p0;
            *(float4*)&sP[g * SPS + kk0 + 4] = p1;
            sW[tid] = Wo[(kt * 64 + g) * 512 + c];
            __syncthreads();
#pragma unroll 8
            for (int kk = 0; kk < 64; kk++)
                acc += sP[g * SPS + kk] * sW[kk * 8 + j];
            __syncthreads();
        }
        out[g * 512 + c] = acc + bo[c];
    } else {
        int i = (b - 64) * 512 + threadIdx.x;
        if (i < N_NODES) g_deg[i] = 0;   // restore invariant for next call
    }
}

// ---------------- launch -------------------------------------------------------
template <typename... Args>
static inline void launch_pdl(void (*kern)(Args...), dim3 grid, dim3 block,
                              Args... args) {
    cudaLaunchAttribute attr;
    attr.id = cudaLaunchAttributeProgrammaticStreamSerialization;
    attr.val.programmaticStreamSerializationAllowed = 1;
    cudaLaunchConfig_t cfg = {};
    cfg.gridDim = grid;
    cfg.blockDim = block;
    cfg.dynamicSmemBytes = 0;
    cfg.stream = 0;
    cfg.attrs = &attr;
    cfg.numAttrs = 1;
    cudaLaunchKernelEx(&cfg, kern, args...);
}

extern "C" void kernel_launch(void* const* d_in, const int* in_sizes, int n_in,
                              void* d_out, int out_size) {
    const float* x     = (const float*)d_in[0];
    const int*   ei    = (const int*)d_in[1];     // int32 (JAX x64 disabled)
    const int*   batch = (const int*)d_in[2];     // int32
    const float* W1    = (const float*)d_in[3];
    const float* as1   = (const float*)d_in[4];
    const float* ad1   = (const float*)d_in[5];
    const float* b1    = (const float*)d_in[6];
    const float* W2    = (const float*)d_in[7];
    const float* as2   = (const float*)d_in[8];
    const float* ad2   = (const float*)d_in[9];
    const float* b2    = (const float*)d_in[10];
    const float* Wo    = (const float*)d_in[11];
    const float* bo    = (const float*)d_in[12];
    float* out = (float*)d_out;

    k_hist_setup<<<470, 256>>>(ei, W2, as2, ad2, batch);   // root: plain launch
    launch_pdl(k_scan_al1, dim3(158), dim3(1024), x, W1, as1, ad1);
    launch_pdl(k_scatter, dim3((E_TOT + 1023) / 1024), dim3(256), ei);
    launch_pdl(k_agg1, dim3((N_NODES * 16) / 256), dim3(256), W1, b1);
    launch_pdl(k_agg2, dim3(N_NODES), dim3(64));
    launch_pdl(k_gemm2, dim3(148), dim3(512), W2, b2, batch);
    launch_pdl(k_final, dim3(64 + (N_NODES + 511) / 512), dim3(512), Wo, bo, out);
}

// round 10
// speedup vs baseline: 1.2975x; 1.2975x over previous
#include <cuda_runtime.h>

#define N_NODES 20000
#define N_EDGES 320000
#define E_TOT   (N_EDGES + N_NODES)
#define N_GRAPHS 64
#define GEMM_TILE 16
#define GPAD 20
#define SPS 68

// ---------------- scratch (device globals; no allocation allowed) ----------
// INVARIANT: g_deg is zero at kernel_launch entry (zero at module load;
// re-zeroed by the tail of k_final). g_pool zeroed by k_hist_setup.
__device__ float  g_als1[N_NODES * 8];
__device__ float  g_ald1[N_NODES * 8];
__device__ float4 g_x4[N_NODES];
__device__ float4 g_o14[N_NODES * 16];
__device__ float4 g_t24[N_NODES * 16];
__device__ float  g_als2[N_NODES];
__device__ float  g_ald2[N_NODES];
__device__ float4 g_va4[16];
__device__ float4 g_vd4[16];
__device__ int    g_deg[N_NODES];
__device__ int    g_fill[N_NODES];       // seeded to rowstart by the scan
__device__ int    g_rowstart[N_NODES + 1];
__device__ int    g_csr[E_TOT];
__device__ float  g_pool[N_GRAPHS * 512];
__device__ int    g_cnt[N_GRAPHS];

// ============ K1: hist(4-edge unroll) + va + counts + pool-zero =============
__global__ void k_hist_setup(const int* __restrict__ ei,
                             const float* __restrict__ W2,
                             const float* __restrict__ as2, const float* __restrict__ ad2,
                             const int* __restrict__ batch) {
    int b = blockIdx.x, t = threadIdx.x;
    if (b < 333) {
        int base = b * 1024 + t;
        int dst[4];
#pragma unroll
        for (int j = 0; j < 4; j++) {
            int e = base + j * 256;
            if (e < E_TOT) dst[j] = (e < N_EDGES) ? ei[N_EDGES + e] : (e - N_EDGES);
            else dst[j] = -1;
        }
#pragma unroll
        for (int j = 0; j < 4; j++)
            if (dst[j] >= 0) atomicAdd(&g_deg[dst[j]], 1);
    } else if (b == 333) {
        if (t >= 32 && t < 96) {
            int g = t - 32;
            int lo = 0, hi = N_NODES;
            while (lo < hi) { int m = (lo + hi) >> 1; if (batch[m] < g) lo = m + 1; else hi = m; }
            int s = lo;
            lo = 0; hi = N_NODES;
            int g1 = g + 1;
            while (lo < hi) { int m = (lo + hi) >> 1; if (batch[m] < g1) lo = m + 1; else hi = m; }
            g_cnt[g] = lo - s;
        }
    } else if (b < 342) {
        int warp = (b - 334) * 8 + (t >> 5);     // 0..63
        int lane = t & 31;
        float s = 0.f, d = 0.f;
        for (int c = lane; c < 512; c += 32) {
            float w = W2[warp * 512 + c];
            s += w * as2[c];
            d += w * ad2[c];
        }
        for (int off = 16; off; off >>= 1) {
            s += __shfl_down_sync(0xffffffffu, s, off);
            d += __shfl_down_sync(0xffffffffu, d, off);
        }
        if (lane == 0) { ((float*)g_va4)[warp] = s; ((float*)g_vd4)[warp] = d; }
    } else {
        int idx = (b - 342) * 256 + t;           // 128*256 == 32768 exactly
        g_pool[idx] = 0.f;
    }
}

// ============ K2: block 0 = coalesced shuffle-scan; blocks 1..157 = al1+x4 ===
__global__ void __launch_bounds__(1024)
k_scan_al1(const float* __restrict__ x, const float* __restrict__ W1,
           const float* __restrict__ as1, const float* __restrict__ ad1) {
    int b = blockIdx.x, t = threadIdx.x;
    if (b == 0) {
        __shared__ int sw[32];
        int lane = t & 31, w = t >> 5;
        int v[20];
#pragma unroll
        for (int k = 0; k < 20; k++) {
            int i = k * 1024 + t;
            v[k] = (i < N_NODES) ? g_deg[i] : 0;
        }
        int running = 0;
#pragma unroll
        for (int k = 0; k < 20; k++) {
            int s = v[k];
#pragma unroll
            for (int off = 1; off < 32; off <<= 1) {
                int n = __shfl_up_sync(0xffffffffu, s, off);
                if (lane >= off) s += n;
            }
            if (lane == 31) sw[w] = s;
            __syncthreads();
            if (w == 0) {
                int p = sw[lane];
#pragma unroll
                for (int off = 1; off < 32; off <<= 1) {
                    int n = __shfl_up_sync(0xffffffffu, p, off);
                    if (lane >= off) p += n;
                }
                sw[lane] = p;
            }
            __syncthreads();
            int ex = running + (w ? sw[w - 1] : 0) + s - v[k];
            int i = k * 1024 + t;
            if (i < N_NODES) { g_rowstart[i] = ex; g_fill[i] = ex; }
            running += sw[31];
            __syncthreads();
        }
        if (t == 0) g_rowstart[N_NODES] = running;
    } else {
        // al1 depends only on harness inputs: compute P locally.
        __shared__ float sPs[24], sPd[24];
        if (t < 24) {
            int h = t / 3, d = t % 3;
            float ps = 0.f, pd = 0.f;
            for (int c = 0; c < 8; c++) {
                float w = W1[d * 64 + h * 8 + c];
                ps += w * as1[h * 8 + c];
                pd += w * ad1[h * 8 + c];
            }
            sPs[t] = ps;
            sPd[t] = pd;
        }
        __syncthreads();
        int idx = (b - 1) * 1024 + t;
        if (idx < N_NODES * 8) {
            int n = idx >> 3, h = idx & 7;
            float x0 = x[n * 3], x1 = x[n * 3 + 1], x2 = x[n * 3 + 2];
            g_als1[idx] = x0 * sPs[h * 3] + x1 * sPs[h * 3 + 1] + x2 * sPs[h * 3 + 2];
            g_ald1[idx] = x0 * sPd[h * 3] + x1 * sPd[h * 3 + 1] + x2 * sPd[h * 3 + 2];
            if (h == 0) g_x4[n] = make_float4(x0, x1, x2, 0.f);
        }
    }
}

// ============ K3: scatter, 4 edges per thread (MLP=4) ========================
__global__ void k_scatter(const int* __restrict__ ei) {
    int base = blockIdx.x * 1024 + threadIdx.x;
    int src[4], dst[4];
#pragma unroll
    for (int j = 0; j < 4; j++) {
        int e = base + j * 256;
        if (e < E_TOT) {
            if (e < N_EDGES) { src[j] = ei[e]; dst[j] = ei[N_EDGES + e]; }
            else             { src[j] = e - N_EDGES; dst[j] = src[j]; }
        } else dst[j] = -1;
    }
#pragma unroll
    for (int j = 0; j < 4; j++) {
        if (dst[j] >= 0) {
            int pos = atomicAdd(&g_fill[dst[j]], 1);
            g_csr[pos] = src[j];
        }
    }
}

// ============ layer-1 aggregate (R6 v3: 16 lanes/node, measured best) ========
__global__ void k_agg1(const float* __restrict__ W1, const float* __restrict__ b1) {
    int gidx = blockIdx.x * 256 + threadIdx.x;    // exactly N_NODES*16 threads
    int n = gidx >> 4;
    int l = gidx & 15;          // lane-in-node
    int h = l >> 1, p = l & 1;  // head, half
    int s0 = g_rowstart[n], s1 = g_rowstart[n + 1];
    int half0 = (s1 - s0 + 1) >> 1;
    int a = p ? (s0 + half0) : s0;
    int bnd = p ? s1 : (s0 + half0);
    float ald = g_ald1[n * 8 + h];
    float wsum = 0.f, xa0 = 0.f, xa1 = 0.f, xa2 = 0.f;
    int i = a;
    for (; i + 2 <= bnd; i += 2) {
        int src0 = g_csr[i], src1 = g_csr[i + 1];
        float e0 = g_als1[src0 * 8 + h] + ald;
        float e1 = g_als1[src1 * 8 + h] + ald;
        float4 xv0 = g_x4[src0];
        float4 xv1 = g_x4[src1];
        e0 = (e0 > 0.f) ? e0 : 0.2f * e0;
        e1 = (e1 > 0.f) ? e1 : 0.2f * e1;
        float w0 = __expf(e0), w1 = __expf(e1);
        wsum += w0 + w1;
        xa0 += w0 * xv0.x + w1 * xv1.x;
        xa1 += w0 * xv0.y + w1 * xv1.y;
        xa2 += w0 * xv0.z + w1 * xv1.z;
    }
    if (i < bnd) {
        int src = g_csr[i];
        float e = g_als1[src * 8 + h] + ald;
        float4 xv = g_x4[src];
        e = (e > 0.f) ? e : 0.2f * e;
        float w = __expf(e);
        wsum += w;
        xa0 += w * xv.x; xa1 += w * xv.y; xa2 += w * xv.z;
    }
    wsum += __shfl_xor_sync(0xffffffffu, wsum, 1);
    xa0  += __shfl_xor_sync(0xffffffffu, xa0, 1);
    xa1  += __shfl_xor_sync(0xffffffffu, xa1, 1);
    xa2  += __shfl_xor_sync(0xffffffffu, xa2, 1);
    float inv = 1.f / wsum;
    xa0 *= inv; xa1 *= inv; xa2 *= inv;
    const float4 w0v = *(const float4*)&W1[4 * l];
    const float4 w1v = *(const float4*)&W1[64 + 4 * l];
    const float4 w2v = *(const float4*)&W1[128 + 4 * l];
    const float4 bv  = *(const float4*)&b1[4 * l];
    float4 o;
    o.x = xa0 * w0v.x + xa1 * w1v.x + xa2 * w2v.x + bv.x;
    o.y = xa0 * w0v.y + xa1 * w1v.y + xa2 * w2v.y + bv.y;
    o.z = xa0 * w0v.z + xa1 * w1v.z + xa2 * w2v.z + bv.z;
    o.w = xa0 * w0v.w + xa1 * w1v.w + xa2 * w2v.w + bv.w;
    o.x = (o.x > 0.f) ? o.x : (__expf(o.x) - 1.f);
    o.y = (o.y > 0.f) ? o.y : (__expf(o.y) - 1.f);
    o.z = (o.z > 0.f) ? o.z : (__expf(o.z) - 1.f);
    o.w = (o.w > 0.f) ? o.w : (__expf(o.w) - 1.f);
    g_o14[n * 16 + l] = o;
    float4 va = g_va4[l], vd = g_vd4[l];
    float ps2 = o.x * va.x + o.y * va.y + o.z * va.z + o.w * va.w;
    float pd2 = o.x * vd.x + o.y * vd.y + o.z * vd.z + o.w * vd.w;
#pragma unroll
    for (int off = 8; off; off >>= 1) {
        ps2 += __shfl_down_sync(0xffffffffu, ps2, off);
        pd2 += __shfl_down_sync(0xffffffffu, pd2, off);
    }
    if (l == 0) { g_als2[n] = ps2; g_ald2[n] = pd2; }
}

// ============ layer-2 aggregate v3: warp-per-node, shfl broadcast, no BAR ====
__global__ void __launch_bounds__(256)
k_agg2() {
    int wid = threadIdx.x >> 5, lane = threadIdx.x & 31;
    int n = blockIdx.x * 8 + wid;                 // 2500*8 == 20000 exactly
    int q = lane & 15, r = lane >> 4;
    int s0 = g_rowstart[n], s1 = g_rowstart[n + 1];
    float ald = g_ald2[n];
    float wsum = 0.f;
    float4 acc = make_float4(0.f, 0.f, 0.f, 0.f);
    for (int base = s0; base < s1; base += 32) {
        int i = base + lane;
        float w = 0.f;
        int src = 0;
        if (i < s1) {
            src = g_csr[i];
            float e = g_als2[src] + ald;
            e = (e > 0.f) ? e : 0.2f * e;
            w = __expf(e);
        }
        wsum += w;
        int m = (s1 - base < 32) ? (s1 - base) : 32;
        // uniform trip count; lanes r=0 handle even j, r=1 odd j
        for (int j0 = 0; j0 < m; j0 += 2) {
            int jj = j0 + r;
            float wj = __shfl_sync(0xffffffffu, w, jj & 31);
            int   sj = __shfl_sync(0xffffffffu, src, jj & 31);
            if (jj < m) {
                float4 v = g_o14[sj * 16 + q];
                acc.x += wj * v.x; acc.y += wj * v.y;
                acc.z += wj * v.z; acc.w += wj * v.w;
            }
        }
    }
    // reduce wsum over the warp
#pragma unroll
    for (int off = 16; off; off >>= 1)
        wsum += __shfl_xor_sync(0xffffffffu, wsum, off);
    // combine the two edge-parity halves (r=0 / r=1)
    acc.x += __shfl_xor_sync(0xffffffffu, acc.x, 16);
    acc.y += __shfl_xor_sync(0xffffffffu, acc.y, 16);
    acc.z += __shfl_xor_sync(0xffffffffu, acc.z, 16);
    acc.w += __shfl_xor_sync(0xffffffffu, acc.w, 16);
    if (r == 0) {
        float inv = 1.f / wsum;
        acc.x *= inv; acc.y *= inv; acc.z *= inv; acc.w *= inv;
        g_t24[n * 16 + q] = acc;
    }
}

// ============ gemm2: persistent, W2 in regs, 16-node tiles, double buffer ====
__global__ void __launch_bounds__(512, 1)
k_gemm2(const float* __restrict__ W2, const float* __restrict__ b2,
        const int* __restrict__ batch) {
    __shared__ __align__(16) float shT[2][64 * GPAD];
    __shared__ int sbat[2][GEMM_TILE];
    const float* t2 = (const float*)g_t24;
    int c = threadIdx.x;
    float w[64];
#pragma unroll
    for (int k = 0; k < 64; k++) w[k] = W2[k * 512 + c];
    float b2c = b2[c];
    const int NT = N_NODES / GEMM_TILE;  // 1250
    int kk = c & 63, np = (c >> 6) * 2;
    int tile = blockIdx.x;
    float r0 = t2[(tile * GEMM_TILE + np) * 64 + kk];
    float r1 = t2[(tile * GEMM_TILE + np + 1) * 64 + kk];
    shT[0][kk * GPAD + np]     = r0;
    shT[0][kk * GPAD + np + 1] = r1;
    if (c < GEMM_TILE) sbat[0][c] = batch[tile * GEMM_TILE + c];
    __syncthreads();
    int buf = 0;
    while (true) {
        int next = tile + (int)gridDim.x;
        bool has_next = (next < NT);
        int nb = 0;
        if (has_next) {
            r0 = t2[(next * GEMM_TILE + np) * 64 + kk];
            r1 = t2[(next * GEMM_TILE + np + 1) * 64 + kk];
            if (c < GEMM_TILE) nb = batch[next * GEMM_TILE + c];
        }
        unsigned long long acc[8];
#pragma unroll
        for (int i = 0; i < 8; i++) acc[i] = 0ull;
#pragma unroll
        for (int k = 0; k < 64; k++) {
            unsigned long long wp;
            asm("mov.b64 %0, {%1, %1};" : "=l"(wp) : "f"(w[k]));
            const ulonglong2* row = reinterpret_cast<const ulonglong2*>(&shT[buf][k * GPAD]);
            ulonglong2 q0 = row[0];
            ulonglong2 q1 = row[1];
            ulonglong2 q2 = row[2];
            ulonglong2 q3 = row[3];
            asm("fma.rn.f32x2 %0, %1, %2, %0;" : "+l"(acc[0]) : "l"(q0.x), "l"(wp));
            asm("fma.rn.f32x2 %0, %1, %2, %0;" : "+l"(acc[1]) : "l"(q0.y), "l"(wp));
            asm("fma.rn.f32x2 %0, %1, %2, %0;" : "+l"(acc[2]) : "l"(q1.x), "l"(wp));
            asm("fma.rn.f32x2 %0, %1, %2, %0;" : "+l"(acc[3]) : "l"(q1.y), "l"(wp));
            asm("fma.rn.f32x2 %0, %1, %2, %0;" : "+l"(acc[4]) : "l"(q2.x), "l"(wp));
            asm("fma.rn.f32x2 %0, %1, %2, %0;" : "+l"(acc[5]) : "l"(q2.y), "l"(wp));
            asm("fma.rn.f32x2 %0, %1, %2, %0;" : "+l"(acc[6]) : "l"(q3.x), "l"(wp));
            asm("fma.rn.f32x2 %0, %1, %2, %0;" : "+l"(acc[7]) : "l"(q3.y), "l"(wp));
        }
        float vals[16];
#pragma unroll
        for (int i = 0; i < 8; i++)
            asm("mov.b64 {%0, %1}, %2;" : "=f"(vals[2 * i]), "=f"(vals[2 * i + 1]) : "l"(acc[i]));
        int bprev = sbat[buf][0];
        float run = 0.f;
#pragma unroll
        for (int i = 0; i < GEMM_TILE; i++) {
            float o = vals[i] + b2c;
            o = (o > 0.f) ? o : (__expf(o) - 1.f);  // elu
            int bg = sbat[buf][i];
            if (bg != bprev) {
                atomicAdd(&g_pool[bprev * 512 + c], run);
                run = 0.f;
                bprev = bg;
            }
            run += o;
        }
        atomicAdd(&g_pool[bprev * 512 + c], run);
        if (!has_next) break;
        int nbuf = buf ^ 1;
        shT[nbuf][kk * GPAD + np]     = r0;
        shT[nbuf][kk * GPAD + np + 1] = r1;
        if (c < GEMM_TILE) sbat[nbuf][c] = nb;
        __syncthreads();
        buf = nbuf;
        tile = next;
    }
}

// ============ final v2: block = 8-col slice x all 64 graphs; Wo read once ====
__global__ void k_final(const float* __restrict__ Wo, const float* __restrict__ bo,
                        float* __restrict__ out) {
    int b = blockIdx.x;
    if (b < 64) {
        __shared__ float sP[64 * SPS];
        __shared__ float sW[64 * 8];
        __shared__ float sInv[64];
        int tid = threadIdx.x;           // 512
        int g = tid >> 3, j = tid & 7;
        int c = b * 8 + j;
        if (tid < 64) sInv[tid] = 1.f / fmaxf((float)g_cnt[tid], 1.f);
        __syncthreads();
        int kk0 = (tid & 7) * 8;
        float invg = sInv[g];
        float acc = 0.f;
#pragma unroll 1
        for (int kt = 0; kt < 8; kt++) {
            float4 p0 = *(const float4*)&g_pool[g * 512 + kt * 64 + kk0];
            float4 p1 = *(const float4*)&g_pool[g * 512 + kt * 64 + kk0 + 4];
            p0.x *= invg; p0.y *= invg; p0.z *= invg; p0.w *= invg;
            p1.x *= invg; p1.y *= invg; p1.z *= invg; p1.w *= invg;
            *(float4*)&sP[g * SPS + kk0]     = p0;
            *(float4*)&sP[g * SPS + kk0 + 4] = p1;
            sW[tid] = Wo[(kt * 64 + g) * 512 + c];
            __syncthreads();
#pragma unroll 8
            for (int kk = 0; kk < 64; kk++)
                acc += sP[g * SPS + kk] * sW[kk * 8 + j];
            __syncthreads();
        }
        out[g * 512 + c] = acc + bo[c];
    } else {
        int i = (b - 64) * 512 + threadIdx.x;
        if (i < N_NODES) g_deg[i] = 0;   // restore invariant for next call
    }
}

// ---------------- launch -------------------------------------------------------
extern "C" void kernel_launch(void* const* d_in, const int* in_sizes, int n_in,
                              void* d_out, int out_size) {
    const float* x     = (const float*)d_in[0];
    const int*   ei    = (const int*)d_in[1];     // int32 (JAX x64 disabled)
    const int*   batch = (const int*)d_in[2];     // int32
    const float* W1    = (const float*)d_in[3];
    const float* as1   = (const float*)d_in[4];
    const float* ad1   = (const float*)d_in[5];
    const float* b1    = (const float*)d_in[6];
    const float* W2    = (const float*)d_in[7];
    const float* as2   = (const float*)d_in[8];
    const float* ad2   = (const float*)d_in[9];
    const float* b2    = (const float*)d_in[10];
    const float* Wo    = (const float*)d_in[11];
    const float* bo    = (const float*)d_in[12];
    float* out = (float*)d_out;

    k_hist_setup<<<470, 256>>>(ei, W2, as2, ad2, batch);
    k_scan_al1<<<158, 1024>>>(x, W1, as1, ad1);
    k_scatter<<<(E_TOT + 1023) / 1024, 256>>>(ei);
    k_agg1<<<(N_NODES * 16) / 256, 256>>>(W1, b1);
    k_agg2<<<N_NODES / 8, 256>>>();
    k_gemm2<<<148, 512>>>(W2, b2, batch);
    k_final<<<64 + (N_NODES + 511) / 512, 512>>>(Wo, bo, out);
}